// round 10
// baseline (speedup 1.0000x reference)
#include <cuda_runtime.h>
#include <cuda_bf16.h>
#include <cstdint>

#define B_   8
#define S_   1024
#define IN_  768
#define H_   8
#define F_   64
#define HF_  512
#define BH_  (B_ * H_)
#define ALPHA_ 0.2f
#define NCH_  32
#define CH_   32

// ---------------------------------------------------------------------------
// Device scratch (no allocations allowed)
// ---------------------------------------------------------------------------
__device__ float  g_Wh[(size_t)B_ * S_ * HF_];
__device__ __nv_bfloat16 g_Xhi[(size_t)B_ * S_ * IN_];
__device__ __nv_bfloat16 g_Xlo[(size_t)B_ * S_ * IN_];
__device__ __nv_bfloat16 g_Wth[(size_t)HF_ * IN_];   // W^T [n][k] hi
__device__ __nv_bfloat16 g_Wtl[(size_t)HF_ * IN_];   // lo

__device__ float4 g_ipack[BH_ * S_];                 // (s, e^s, e^{as}, 0)
__device__ float4 g_jpack[BH_ * S_];                 // (d, m e^d, m e^{ad}, 0)

__device__ float  g_dsorted[BH_][S_];
__device__ int    g_perm[BH_][S_];
__device__ float  g_e1ds[BH_][S_];
__device__ float  g_eads[BH_][S_];

__device__ __align__(16) float g_Q0[BH_][S_ + 1][68];
__device__ __align__(16) float g_Q1[BH_][S_ + 1][68];
__device__ float g_csum0[BH_][NCH_][68];             // raw chunk sums (scanA)
__device__ float g_csum1[BH_][NCH_][68];

// ---------------------------------------------------------------------------
// PTX helpers (baseline sm_80+ features only: valid on family target sm_103)
// ---------------------------------------------------------------------------
__device__ __forceinline__ uint32_t smem_u32(const void* p) {
    uint32_t a;
    asm("{ .reg .u64 t; cvta.to.shared.u64 t, %1; cvt.u32.u64 %0, t; }"
        : "=r"(a) : "l"(p));
    return a;
}
__device__ __forceinline__ unsigned long long gmem_u64(const void* p) {
    unsigned long long a;
    asm("cvta.to.global.u64 %0, %1;" : "=l"(a) : "l"(p));
    return a;
}
#define CP_ASYNC16(s, g) \
    asm volatile("cp.async.cg.shared.global [%0], [%1], 16;" :: "r"(s), "l"(g) : "memory")
#define CP_COMMIT() asm volatile("cp.async.commit_group;" ::: "memory")
#define CP_WAIT0()  asm volatile("cp.async.wait_group 0;" ::: "memory")

#define LDX4(r, addr) \
    asm volatile("ldmatrix.sync.aligned.m8n8.x4.shared.b16 {%0,%1,%2,%3}, [%4];" \
                 : "=r"((r)[0]), "=r"((r)[1]), "=r"((r)[2]), "=r"((r)[3]) : "r"(addr))

#define MMA_BF16(cc, a, b0, b1) \
    asm volatile("mma.sync.aligned.m16n8k16.row.col.f32.bf16.bf16.f32 " \
                 "{%0,%1,%2,%3}, {%4,%5,%6,%7}, {%8,%9}, {%0,%1,%2,%3};" \
                 : "+f"((cc)[0]), "+f"((cc)[1]), "+f"((cc)[2]), "+f"((cc)[3]) \
                 : "r"((a)[0]), "r"((a)[1]), "r"((a)[2]), "r"((a)[3]), "r"(b0), "r"(b1))

// ---------------------------------------------------------------------------
// K0a: split X into bf16 hi/lo
// ---------------------------------------------------------------------------
__global__ void __launch_bounds__(256) convX_kernel(const float* __restrict__ X)
{
    const size_t i = ((size_t)blockIdx.x * 256 + threadIdx.x) * 4;
    float4 v = *(const float4*)(X + i);
    __nv_bfloat16 h0 = __float2bfloat16(v.x), h1 = __float2bfloat16(v.y);
    __nv_bfloat16 h2 = __float2bfloat16(v.z), h3 = __float2bfloat16(v.w);
    __nv_bfloat16 l0 = __float2bfloat16(v.x - __bfloat162float(h0));
    __nv_bfloat16 l1 = __float2bfloat16(v.y - __bfloat162float(h1));
    __nv_bfloat16 l2 = __float2bfloat16(v.z - __bfloat162float(h2));
    __nv_bfloat16 l3 = __float2bfloat16(v.w - __bfloat162float(h3));
    *(__nv_bfloat162*)(g_Xhi + i)     = __nv_bfloat162(h0, h1);
    *(__nv_bfloat162*)(g_Xhi + i + 2) = __nv_bfloat162(h2, h3);
    *(__nv_bfloat162*)(g_Xlo + i)     = __nv_bfloat162(l0, l1);
    *(__nv_bfloat162*)(g_Xlo + i + 2) = __nv_bfloat162(l2, l3);
}

// ---------------------------------------------------------------------------
// K0b: transpose + split W -> Wt[n][k] hi/lo
// ---------------------------------------------------------------------------
__global__ void __launch_bounds__(256) convW_kernel(const float* __restrict__ W)
{
    __shared__ float tile[32][33];
    const int kb = blockIdx.x * 32;
    const int nb = blockIdx.y * 32;
    const int tx = threadIdx.x & 31, ty = threadIdx.x >> 5;
#pragma unroll
    for (int r = ty; r < 32; r += 8)
        tile[r][tx] = W[(size_t)(kb + r) * HF_ + nb + tx];
    __syncthreads();
#pragma unroll
    for (int r = ty; r < 32; r += 8) {
        float x = tile[tx][r];
        __nv_bfloat16 h = __float2bfloat16(x);
        g_Wth[(size_t)(nb + r) * IN_ + kb + tx] = h;
        g_Wtl[(size_t)(nb + r) * IN_ + kb + tx] = __float2bfloat16(x - __bfloat162float(h));
    }
}

// ---------------------------------------------------------------------------
// K1: split-bf16 HMMA GEMM, CTA 128x128, 8 warps, BK=32, double-buffered
// cp.async — with FUSED srcdst epilogue (each warp's 64-col tile = one head).
// ---------------------------------------------------------------------------
#define STG_    40960
#define AHI_    0
#define ALO_    10240
#define BHI_    20480
#define BLO_    30720
#define NSTAGE_ (IN_ / 32)   // 24

__global__ void __launch_bounds__(256) mma_gemm_kernel(const int* __restrict__ mask,
                                                       const float* __restrict__ avec)
{
    extern __shared__ __align__(16) char smem[];
    __shared__ float s_asrc[64], s_adst[64];

    const int t = threadIdx.x;
    const int wid = t >> 5;
    const int lane = t & 31;
    const int warp_m = wid >> 1;
    const int warp_n = wid & 1;
    const int i0 = blockIdx.x * 128;
    const int f0 = blockIdx.y * 128;
    const uint32_t sb0 = smem_u32(smem);

    if (t < 64)       s_asrc[t]      = avec[t];
    else if (t < 128) s_adst[t - 64] = avec[t];

    float acc[2][8][4];
#pragma unroll
    for (int mt = 0; mt < 2; mt++)
#pragma unroll
        for (int nt = 0; nt < 8; nt++)
#pragma unroll
            for (int q = 0; q < 4; q++) acc[mt][nt][q] = 0.f;

    auto load_stage = [&](int ch, int s) {
        const uint32_t st = sb0 + s * STG_;
        const int k0 = ch * 32;
#pragma unroll
        for (int p = t; p < 512; p += 256) {
            const int row = p >> 2, q = p & 3;
            const uint32_t so = st + row * 80 + q * 16;
            const size_t ga = (size_t)(i0 + row) * IN_ + k0 + q * 8;
            const size_t gb = (size_t)(f0 + row) * IN_ + k0 + q * 8;
            CP_ASYNC16(so + AHI_, gmem_u64(g_Xhi + ga));
            CP_ASYNC16(so + ALO_, gmem_u64(g_Xlo + ga));
            CP_ASYNC16(so + BHI_, gmem_u64(g_Wth + gb));
            CP_ASYNC16(so + BLO_, gmem_u64(g_Wtl + gb));
        }
        CP_COMMIT();
    };

    load_stage(0, 0);

    const uint32_t a_lane_off = (lane & 15) * 80 + (lane >> 4) * 16;

    for (int ch = 0; ch < NSTAGE_; ch++) {
        CP_WAIT0();
        __syncthreads();
        if (ch + 1 < NSTAGE_) load_stage(ch + 1, (ch + 1) & 1);

        const uint32_t st = sb0 + (ch & 1) * STG_;
#pragma unroll
        for (int kt = 0; kt < 2; kt++) {
            uint32_t ah[2][4], al[2][4];
#pragma unroll
            for (int mt = 0; mt < 2; mt++) {
                const uint32_t aa = st + AHI_ + (warp_m * 32 + mt * 16) * 80
                                  + kt * 32 + a_lane_off;
                LDX4(ah[mt], aa);
                LDX4(al[mt], aa + (ALO_ - AHI_));
            }
#pragma unroll
            for (int nt = 0; nt < 4; nt++) {
                uint32_t bh[4], bl[4];
                const uint32_t ba = st + BHI_ + (warp_n * 64 + nt * 16) * 80
                                  + kt * 32 + a_lane_off;
                LDX4(bh, ba);
                LDX4(bl, ba + (BLO_ - BHI_));
#pragma unroll
                for (int mt = 0; mt < 2; mt++) {
                    MMA_BF16(acc[mt][nt * 2],     ah[mt], bh[0], bh[2]);
                    MMA_BF16(acc[mt][nt * 2],     al[mt], bh[0], bh[2]);
                    MMA_BF16(acc[mt][nt * 2],     ah[mt], bl[0], bl[2]);
                    MMA_BF16(acc[mt][nt * 2 + 1], ah[mt], bh[1], bh[3]);
                    MMA_BF16(acc[mt][nt * 2 + 1], al[mt], bh[1], bh[3]);
                    MMA_BF16(acc[mt][nt * 2 + 1], ah[mt], bl[1], bl[3]);
                }
            }
        }
        __syncthreads();
    }

    // ---- epilogue 1: store Wh ----
#pragma unroll
    for (int mt = 0; mt < 2; mt++) {
        const int r0 = i0 + warp_m * 32 + mt * 16 + (lane >> 2);
#pragma unroll
        for (int nt = 0; nt < 8; nt++) {
            const int c = f0 + warp_n * 64 + nt * 8 + (lane & 3) * 2;
            *(float2*)(g_Wh + (size_t)r0 * HF_ + c) =
                make_float2(acc[mt][nt][0], acc[mt][nt][1]);
            *(float2*)(g_Wh + (size_t)(r0 + 8) * HF_ + c) =
                make_float2(acc[mt][nt][2], acc[mt][nt][3]);
        }
    }

    // ---- epilogue 2 (fused srcdst): warp tile = one full head (64 cols) ----
    const int h = blockIdx.y * 2 + warp_n;
    const int lq = lane & 3;
    float sp[4], dp[4];           // (mt, row-half): {mt0 r, mt0 r+8, mt1 r, mt1 r+8}
#pragma unroll
    for (int mt = 0; mt < 2; mt++)
#pragma unroll
        for (int hf = 0; hf < 2; hf++) {
            float s = 0.f, d = 0.f;
#pragma unroll
            for (int nt = 0; nt < 8; nt++) {
                const int fi = nt * 8 + lq * 2;
                const float c0 = acc[mt][nt][hf * 2], c1 = acc[mt][nt][hf * 2 + 1];
                s += c0 * s_asrc[fi] + c1 * s_asrc[fi + 1];
                d += c0 * s_adst[fi] + c1 * s_adst[fi + 1];
            }
            sp[mt * 2 + hf] = s;
            dp[mt * 2 + hf] = d;
        }
#pragma unroll
    for (int q = 0; q < 4; q++) {
        sp[q] += __shfl_xor_sync(0xffffffffu, sp[q], 1);
        sp[q] += __shfl_xor_sync(0xffffffffu, sp[q], 2);
        dp[q] += __shfl_xor_sync(0xffffffffu, dp[q], 1);
        dp[q] += __shfl_xor_sync(0xffffffffu, dp[q], 2);
    }
    if (lq == 0) {
#pragma unroll
        for (int q = 0; q < 4; q++) {
            const int mt = q >> 1, hf = q & 1;
            const int row = i0 + warp_m * 32 + mt * 16 + hf * 8 + (lane >> 2);
            const int b = row >> 10, i = row & 1023;
            const int idx = (b * H_ + h) * S_ + i;
            const float s = sp[q], d = dp[q];
            g_ipack[idx] = make_float4(s, expf(s), expf(ALPHA_ * s), 0.f);
            const float m = mask[row] ? 1.f : 0.f;
            g_jpack[idx] = make_float4(d, m * expf(d), m * expf(ALPHA_ * d), 0.f);
        }
    }
}

// ---------------------------------------------------------------------------
// K3a: per (b,h): bitonic sort, packed u64 (sortable-key<<32 | idx).
// ---------------------------------------------------------------------------
__global__ void __launch_bounds__(1024) sort_kernel()
{
    __shared__ unsigned long long sv[S_];
    const int bh = blockIdx.x;
    const int t  = threadIdx.x;

    {
        const uint32_t u = __float_as_uint(g_jpack[bh * S_ + t].x);
        const uint32_t s = (u & 0x80000000u) ? ~u : (u ^ 0x80000000u);
        sv[t] = ((unsigned long long)s << 32) | (unsigned)t;
    }
    __syncthreads();

    for (int k = 2; k <= S_; k <<= 1) {
        for (int j = k >> 1; j > 0; j >>= 1) {
            const int ixj = t ^ j;
            if (ixj > t) {
                const bool up = ((t & k) == 0);
                const unsigned long long a = sv[t], b = sv[ixj];
                if (up ? (a > b) : (a < b)) { sv[t] = b; sv[ixj] = a; }
            }
            __syncthreads();
        }
    }

    const unsigned long long v = sv[t];
    const int p = (int)(v & 0xFFFFFFFFu);
    const uint32_t s = (uint32_t)(v >> 32);
    const uint32_t u = (s & 0x80000000u) ? (s ^ 0x80000000u) : ~s;
    float4 jp = g_jpack[bh * S_ + p];
    g_dsorted[bh][t] = __uint_as_float(u);
    g_perm[bh][t]    = p;
    g_e1ds[bh][t]    = jp.y;
    g_eads[bh][t]    = jp.z;
}

// ---------------------------------------------------------------------------
// K3b-A: raw chunk partial sums. Block = (bh, chunk), 96 threads (c < 65).
// ---------------------------------------------------------------------------
__global__ void __launch_bounds__(96) scanA_kernel()
{
    __shared__ int   sp[CH_];
    __shared__ float sw0[CH_], sw1[CH_];
    const int bh = blockIdx.x;
    const int ch = blockIdx.y;
    const int b = bh >> 3, h = bh & 7;
    const int t = threadIdx.x;

    if (t < CH_) {
        const int kk = ch * CH_ + t;
        sp[t]  = g_perm[bh][kk] * HF_;
        sw0[t] = g_eads[bh][kk];
        sw1[t] = g_e1ds[bh][kk];
    }
    __syncthreads();
    if (t >= 65) return;

    const float* __restrict__ whb = g_Wh + (size_t)b * S_ * HF_ + h * F_ + t;
    const bool feat = (t < 64);
    float s0 = 0.f, s1 = 0.f;
#pragma unroll
    for (int k = 0; k < CH_; k++) {
        const float v = feat ? __ldg(whb + sp[k]) : 1.f;
        s0 += sw0[k] * v;
        s1 += sw1[k] * v;
    }
    g_csum0[bh][ch][t] = s0;
    g_csum1[bh][ch][t] = s1;
}

// ---------------------------------------------------------------------------
// K3b-C: materialize Q0/Q1. Each block sums the preceding raw chunk sums
// itself (scanB eliminated). Block = (bh, chunk), 96 threads.
// ---------------------------------------------------------------------------
__global__ void __launch_bounds__(96) scanC_kernel()
{
    __shared__ int   sp[CH_];
    __shared__ float sw0[CH_], sw1[CH_];
    const int bh = blockIdx.x;
    const int ch = blockIdx.y;
    const int b = bh >> 3, h = bh & 7;
    const int t = threadIdx.x;

    if (t < CH_) {
        const int kk = ch * CH_ + t;
        sp[t]  = g_perm[bh][kk] * HF_;
        sw0[t] = g_eads[bh][kk];
        sw1[t] = g_e1ds[bh][kk];
    }
    __syncthreads();
    if (t >= 65) return;

    float off0 = 0.f, off1 = 0.f;
    for (int c2 = 0; c2 < ch; c2++) {
        off0 += g_csum0[bh][c2][t];
        off1 += g_csum1[bh][c2][t];
    }

    const float* __restrict__ whb = g_Wh + (size_t)b * S_ * HF_ + h * F_ + t;
    const bool feat = (t < 64);
    const int k0 = ch * CH_;
#pragma unroll
    for (int k = 0; k < CH_; k++) {
        g_Q0[bh][k0 + k][t] = off0;
        g_Q1[bh][k0 + k][t] = off1;
        const float v = feat ? __ldg(whb + sp[k]) : 1.f;
        off0 += sw0[k] * v;
        off1 += sw1[k] * v;
    }
    if (ch == NCH_ - 1) {
        g_Q0[bh][S_][t] = off0;
        g_Q1[bh][S_][t] = off1;
    }
}

// ---------------------------------------------------------------------------
// K4: epilogue. Binary search split point; combine prefix/suffix; normalize.
// ---------------------------------------------------------------------------
__global__ void __launch_bounds__(256) out_kernel(float* __restrict__ out)
{
    __shared__ float ds[S_];
    const int b = blockIdx.z, h = blockIdx.y;
    const int bh = b * H_ + h;
    const int t = threadIdx.x;

    for (int q = t; q < S_; q += 256) ds[q] = g_dsorted[bh][q];
    __syncthreads();

    const int c4 = t & 15;
    const int il = t >> 4;
    const int i  = blockIdx.x * 16 + il;

    float4 ip = g_ipack[bh * S_ + i];
    const float e1s = ip.y, eas = ip.z;
    const float thr = -ip.x;

    int lo = 0, hi = S_;
    while (lo < hi) {
        int mid = (lo + hi) >> 1;
        if (ds[mid] < thr) lo = mid + 1; else hi = mid;
    }

    const float* q0 = &g_Q0[bh][lo][0];
    const float* q1 = &g_Q1[bh][lo][0];
    const float* t1 = &g_Q1[bh][S_][0];

    float4 n4 = *(const float4*)(q0 + c4 * 4);
    float4 q4 = *(const float4*)(q1 + c4 * 4);
    float4 t4 = *(const float4*)(t1 + c4 * 4);
    const float zpos = t1[64] - q1[64];
    const float inv = 1.f / (eas * q0[64] + e1s * zpos);

    float4 o;
    o.x = (eas * n4.x + e1s * (t4.x - q4.x)) * inv;
    o.y = (eas * n4.y + e1s * (t4.y - q4.y)) * inv;
    o.z = (eas * n4.z + e1s * (t4.z - q4.z)) * inv;
    o.w = (eas * n4.w + e1s * (t4.w - q4.w)) * inv;
    *(float4*)(out + (size_t)(b * S_ + i) * HF_ + h * F_ + c4 * 4) = o;
}

// ---------------------------------------------------------------------------
extern "C" void kernel_launch(void* const* d_in, const int* in_sizes, int n_in,
                              void* d_out, int out_size)
{
    const float* X    = (const float*)d_in[0];
    const int*   mask = (const int*)  d_in[1];
    const float* W    = (const float*)d_in[2];
    const float* a    = (const float*)d_in[3];
    float*       out  = (float*)d_out;

    static bool attr_set = false;
    if (!attr_set) {
        cudaFuncSetAttribute(mma_gemm_kernel,
                             cudaFuncAttributeMaxDynamicSharedMemorySize, 2 * STG_);
        attr_set = true;
    }

    convX_kernel<<<(B_ * S_ * IN_) / (256 * 4), 256>>>(X);
    convW_kernel<<<dim3(IN_ / 32, HF_ / 32), 256>>>(W);
    mma_gemm_kernel<<<dim3((B_ * S_) / 128, HF_ / 128), 256, 2 * STG_>>>(mask, a);
    sort_kernel<<<BH_, 1024>>>();
    scanA_kernel<<<dim3(BH_, NCH_), 96>>>();
    scanC_kernel<<<dim3(BH_, NCH_), 96>>>();
    out_kernel<<<dim3(S_ / 16, H_, B_), 256>>>(out);
}

// round 13
// speedup vs baseline: 1.4791x; 1.4791x over previous
#include <cuda_runtime.h>
#include <cuda_bf16.h>
#include <cstdint>

#define B_   8
#define S_   1024
#define IN_  768
#define H_   8
#define F_   64
#define HF_  512
#define BH_  (B_ * H_)
#define ALPHA_ 0.2f
#define NCH_  32
#define CH_   32

// ---------------------------------------------------------------------------
// Device scratch (no allocations allowed)
// ---------------------------------------------------------------------------
__device__ float  g_Wh[(size_t)B_ * S_ * HF_];
__device__ __nv_bfloat16 g_Xhi[(size_t)B_ * S_ * IN_];
__device__ __nv_bfloat16 g_Xlo[(size_t)B_ * S_ * IN_];
__device__ __nv_bfloat16 g_Wth[(size_t)HF_ * IN_];   // W^T [n][k] hi
__device__ __nv_bfloat16 g_Wtl[(size_t)HF_ * IN_];   // lo

__device__ float4 g_ipack[BH_ * S_];                 // (s, e^s, e^{as}, 0)
__device__ float4 g_jpack[BH_ * S_];                 // (d, m e^d, m e^{ad}, 0)

__device__ float  g_dsorted[BH_][S_];
__device__ int    g_perm[BH_][S_];
__device__ float  g_e1ds[BH_][S_];
__device__ float  g_eads[BH_][S_];

__device__ __align__(16) float g_Q0[BH_][S_ + 1][68];
__device__ __align__(16) float g_Q1[BH_][S_ + 1][68];
__device__ float g_csum0[BH_][NCH_][68];             // raw chunk sums (scanA)
__device__ float g_csum1[BH_][NCH_][68];

// ---------------------------------------------------------------------------
// PTX helpers (baseline sm_80+ features only: valid on family target sm_103)
// ---------------------------------------------------------------------------
__device__ __forceinline__ uint32_t smem_u32(const void* p) {
    uint32_t a;
    asm("{ .reg .u64 t; cvta.to.shared.u64 t, %1; cvt.u32.u64 %0, t; }"
        : "=r"(a) : "l"(p));
    return a;
}
__device__ __forceinline__ unsigned long long gmem_u64(const void* p) {
    unsigned long long a;
    asm("cvta.to.global.u64 %0, %1;" : "=l"(a) : "l"(p));
    return a;
}
#define CP_ASYNC16(s, g) \
    asm volatile("cp.async.cg.shared.global [%0], [%1], 16;" :: "r"(s), "l"(g) : "memory")
#define CP_COMMIT() asm volatile("cp.async.commit_group;" ::: "memory")
#define CP_WAIT0()  asm volatile("cp.async.wait_group 0;" ::: "memory")

#define LDX4(r, addr) \
    asm volatile("ldmatrix.sync.aligned.m8n8.x4.shared.b16 {%0,%1,%2,%3}, [%4];" \
                 : "=r"((r)[0]), "=r"((r)[1]), "=r"((r)[2]), "=r"((r)[3]) : "r"(addr))

#define MMA_BF16(cc, a, b0, b1) \
    asm volatile("mma.sync.aligned.m16n8k16.row.col.f32.bf16.bf16.f32 " \
                 "{%0,%1,%2,%3}, {%4,%5,%6,%7}, {%8,%9}, {%0,%1,%2,%3};" \
                 : "+f"((cc)[0]), "+f"((cc)[1]), "+f"((cc)[2]), "+f"((cc)[3]) \
                 : "r"((a)[0]), "r"((a)[1]), "r"((a)[2]), "r"((a)[3]), "r"(b0), "r"(b1))

// ---------------------------------------------------------------------------
// K0a: split X into bf16 hi/lo
// ---------------------------------------------------------------------------
__global__ void __launch_bounds__(256) convX_kernel(const float* __restrict__ X)
{
    const size_t i = ((size_t)blockIdx.x * 256 + threadIdx.x) * 4;
    float4 v = *(const float4*)(X + i);
    __nv_bfloat16 h0 = __float2bfloat16(v.x), h1 = __float2bfloat16(v.y);
    __nv_bfloat16 h2 = __float2bfloat16(v.z), h3 = __float2bfloat16(v.w);
    __nv_bfloat16 l0 = __float2bfloat16(v.x - __bfloat162float(h0));
    __nv_bfloat16 l1 = __float2bfloat16(v.y - __bfloat162float(h1));
    __nv_bfloat16 l2 = __float2bfloat16(v.z - __bfloat162float(h2));
    __nv_bfloat16 l3 = __float2bfloat16(v.w - __bfloat162float(h3));
    *(__nv_bfloat162*)(g_Xhi + i)     = __nv_bfloat162(h0, h1);
    *(__nv_bfloat162*)(g_Xhi + i + 2) = __nv_bfloat162(h2, h3);
    *(__nv_bfloat162*)(g_Xlo + i)     = __nv_bfloat162(l0, l1);
    *(__nv_bfloat162*)(g_Xlo + i + 2) = __nv_bfloat162(l2, l3);
}

// ---------------------------------------------------------------------------
// K0b: transpose + split W -> Wt[n][k] hi/lo
// ---------------------------------------------------------------------------
__global__ void __launch_bounds__(256) convW_kernel(const float* __restrict__ W)
{
    __shared__ float tile[32][33];
    const int kb = blockIdx.x * 32;
    const int nb = blockIdx.y * 32;
    const int tx = threadIdx.x & 31, ty = threadIdx.x >> 5;
#pragma unroll
    for (int r = ty; r < 32; r += 8)
        tile[r][tx] = W[(size_t)(kb + r) * HF_ + nb + tx];
    __syncthreads();
#pragma unroll
    for (int r = ty; r < 32; r += 8) {
        float x = tile[tx][r];
        __nv_bfloat16 h = __float2bfloat16(x);
        g_Wth[(size_t)(nb + r) * IN_ + kb + tx] = h;
        g_Wtl[(size_t)(nb + r) * IN_ + kb + tx] = __float2bfloat16(x - __bfloat162float(h));
    }
}

// ---------------------------------------------------------------------------
// K1: split-bf16 HMMA GEMM, CTA 128x128, 8 warps, BK=32, double-buffered
// cp.async, fused srcdst epilogue. __launch_bounds__(256,2) keeps <=128 regs
// so 2 CTAs/SM co-reside (the R10 regression was losing this).
// ---------------------------------------------------------------------------
#define STG_    40960
#define AHI_    0
#define ALO_    10240
#define BHI_    20480
#define BLO_    30720
#define NSTAGE_ (IN_ / 32)   // 24

__global__ void __launch_bounds__(256, 2) mma_gemm_kernel(const int* __restrict__ mask,
                                                          const float* __restrict__ avec)
{
    extern __shared__ __align__(16) char smem[];
    __shared__ float s_asrc[64], s_adst[64];

    const int t = threadIdx.x;
    const int wid = t >> 5;
    const int lane = t & 31;
    const int warp_m = wid >> 1;
    const int warp_n = wid & 1;
    const int i0 = blockIdx.x * 128;
    const int f0 = blockIdx.y * 128;
    const uint32_t sb0 = smem_u32(smem);

    if (t < 64)       s_asrc[t]      = avec[t];
    else if (t < 128) s_adst[t - 64] = avec[t];

    float acc[2][8][4];
#pragma unroll
    for (int mt = 0; mt < 2; mt++)
#pragma unroll
        for (int nt = 0; nt < 8; nt++)
#pragma unroll
            for (int q = 0; q < 4; q++) acc[mt][nt][q] = 0.f;

    auto load_stage = [&](int ch, int s) {
        const uint32_t st = sb0 + s * STG_;
        const int k0 = ch * 32;
#pragma unroll
        for (int p = t; p < 512; p += 256) {
            const int row = p >> 2, q = p & 3;
            const uint32_t so = st + row * 80 + q * 16;
            const size_t ga = (size_t)(i0 + row) * IN_ + k0 + q * 8;
            const size_t gb = (size_t)(f0 + row) * IN_ + k0 + q * 8;
            CP_ASYNC16(so + AHI_, gmem_u64(g_Xhi + ga));
            CP_ASYNC16(so + ALO_, gmem_u64(g_Xlo + ga));
            CP_ASYNC16(so + BHI_, gmem_u64(g_Wth + gb));
            CP_ASYNC16(so + BLO_, gmem_u64(g_Wtl + gb));
        }
        CP_COMMIT();
    };

    load_stage(0, 0);

    const uint32_t a_lane_off = (lane & 15) * 80 + (lane >> 4) * 16;

    for (int ch = 0; ch < NSTAGE_; ch++) {
        CP_WAIT0();
        __syncthreads();
        if (ch + 1 < NSTAGE_) load_stage(ch + 1, (ch + 1) & 1);

        const uint32_t st = sb0 + (ch & 1) * STG_;
#pragma unroll
        for (int kt = 0; kt < 2; kt++) {
            uint32_t ah[2][4], al[2][4];
#pragma unroll
            for (int mt = 0; mt < 2; mt++) {
                const uint32_t aa = st + AHI_ + (warp_m * 32 + mt * 16) * 80
                                  + kt * 32 + a_lane_off;
                LDX4(ah[mt], aa);
                LDX4(al[mt], aa + (ALO_ - AHI_));
            }
#pragma unroll
            for (int nt = 0; nt < 4; nt++) {
                uint32_t bh[4], bl[4];
                const uint32_t ba = st + BHI_ + (warp_n * 64 + nt * 16) * 80
                                  + kt * 32 + a_lane_off;
                LDX4(bh, ba);
                LDX4(bl, ba + (BLO_ - BHI_));
#pragma unroll
                for (int mt = 0; mt < 2; mt++) {
                    MMA_BF16(acc[mt][nt * 2],     ah[mt], bh[0], bh[2]);
                    MMA_BF16(acc[mt][nt * 2],     al[mt], bh[0], bh[2]);
                    MMA_BF16(acc[mt][nt * 2],     ah[mt], bl[0], bl[2]);
                    MMA_BF16(acc[mt][nt * 2 + 1], ah[mt], bh[1], bh[3]);
                    MMA_BF16(acc[mt][nt * 2 + 1], al[mt], bh[1], bh[3]);
                    MMA_BF16(acc[mt][nt * 2 + 1], ah[mt], bl[1], bl[3]);
                }
            }
        }
        __syncthreads();
    }

    // ---- epilogue 1: store Wh ----
#pragma unroll
    for (int mt = 0; mt < 2; mt++) {
        const int r0 = i0 + warp_m * 32 + mt * 16 + (lane >> 2);
#pragma unroll
        for (int nt = 0; nt < 8; nt++) {
            const int c = f0 + warp_n * 64 + nt * 8 + (lane & 3) * 2;
            *(float2*)(g_Wh + (size_t)r0 * HF_ + c) =
                make_float2(acc[mt][nt][0], acc[mt][nt][1]);
            *(float2*)(g_Wh + (size_t)(r0 + 8) * HF_ + c) =
                make_float2(acc[mt][nt][2], acc[mt][nt][3]);
        }
    }

    // ---- epilogue 2 (fused srcdst): warp tile = one full head (64 cols) ----
    const int h = blockIdx.y * 2 + warp_n;
    const int lq = lane & 3;
    float sp[4], dp[4];
#pragma unroll
    for (int mt = 0; mt < 2; mt++)
#pragma unroll
        for (int hf = 0; hf < 2; hf++) {
            float s = 0.f, d = 0.f;
#pragma unroll
            for (int nt = 0; nt < 8; nt++) {
                const int fi = nt * 8 + lq * 2;
                const float c0 = acc[mt][nt][hf * 2], c1 = acc[mt][nt][hf * 2 + 1];
                s += c0 * s_asrc[fi] + c1 * s_asrc[fi + 1];
                d += c0 * s_adst[fi] + c1 * s_adst[fi + 1];
            }
            sp[mt * 2 + hf] = s;
            dp[mt * 2 + hf] = d;
        }
#pragma unroll
    for (int q = 0; q < 4; q++) {
        sp[q] += __shfl_xor_sync(0xffffffffu, sp[q], 1);
        sp[q] += __shfl_xor_sync(0xffffffffu, sp[q], 2);
        dp[q] += __shfl_xor_sync(0xffffffffu, dp[q], 1);
        dp[q] += __shfl_xor_sync(0xffffffffu, dp[q], 2);
    }
    if (lq == 0) {
#pragma unroll
        for (int q = 0; q < 4; q++) {
            const int mt = q >> 1, hf = q & 1;
            const int row = i0 + warp_m * 32 + mt * 16 + hf * 8 + (lane >> 2);
            const int b = row >> 10, i = row & 1023;
            const int idx = (b * H_ + h) * S_ + i;
            const float s = sp[q], d = dp[q];
            g_ipack[idx] = make_float4(s, expf(s), expf(ALPHA_ * s), 0.f);
            const float m = mask[row] ? 1.f : 0.f;
            g_jpack[idx] = make_float4(d, m * expf(d), m * expf(ALPHA_ * d), 0.f);
        }
    }
}

// ---------------------------------------------------------------------------
// K3a: hybrid bitonic sort on packed u64: intra-warp sub-stages (j<=16) via
// shfl in registers, only j>=32 passes through smem. 15 smem passes vs 55.
// ---------------------------------------------------------------------------
__device__ __forceinline__ unsigned long long
bitonic_warp_tail(unsigned long long v, int t, int k, int jmax)
{
    const bool up = ((t & k) == 0);
#pragma unroll
    for (int j = 16; j > 0; j >>= 1) {
        if (j > jmax) continue;
        const unsigned long long p = __shfl_xor_sync(0xffffffffu, v, j);
        const bool lower = ((t & j) == 0);
        const bool keep_min = (lower == up);
        v = keep_min ? (v < p ? v : p) : (v > p ? v : p);
    }
    return v;
}

__global__ void __launch_bounds__(1024) sort_kernel()
{
    __shared__ unsigned long long sv[S_];
    const int bh = blockIdx.x;
    const int t  = threadIdx.x;

    unsigned long long v;
    {
        const uint32_t u = __float_as_uint(g_jpack[bh * S_ + t].x);
        const uint32_t s = (u & 0x80000000u) ? ~u : (u ^ 0x80000000u);
        v = ((unsigned long long)s << 32) | (unsigned)t;
    }

    // stages k = 2..32 entirely in registers (all j <= 16)
#pragma unroll
    for (int k = 2; k <= 32; k <<= 1)
        v = bitonic_warp_tail(v, t, k, k >> 1);

    sv[t] = v;
    __syncthreads();

    // stages k = 64..1024: smem passes for j >= 32, register tail for j <= 16
    for (int k = 64; k <= S_; k <<= 1) {
        for (int j = k >> 1; j >= 32; j >>= 1) {
            const int ixj = t ^ j;
            if (ixj > t) {
                const bool up = ((t & k) == 0);
                const unsigned long long a = sv[t], b2 = sv[ixj];
                if (up ? (a > b2) : (a < b2)) { sv[t] = b2; sv[ixj] = a; }
            }
            __syncthreads();
        }
        v = sv[t];
        v = bitonic_warp_tail(v, t, k, 16);
        sv[t] = v;
        __syncthreads();
    }

    const int p = (int)(v & 0xFFFFFFFFu);
    const uint32_t s = (uint32_t)(v >> 32);
    const uint32_t u = (s & 0x80000000u) ? (s ^ 0x80000000u) : ~s;
    float4 jp = g_jpack[bh * S_ + p];
    g_dsorted[bh][t] = __uint_as_float(u);
    g_perm[bh][t]    = p;
    g_e1ds[bh][t]    = jp.y;
    g_eads[bh][t]    = jp.z;
}

// ---------------------------------------------------------------------------
// K3b-A: raw chunk partial sums. Block = (bh, chunk), 96 threads (c < 65).
// ---------------------------------------------------------------------------
__global__ void __launch_bounds__(96) scanA_kernel()
{
    __shared__ int   sp[CH_];
    __shared__ float sw0[CH_], sw1[CH_];
    const int bh = blockIdx.x;
    const int ch = blockIdx.y;
    const int b = bh >> 3, h = bh & 7;
    const int t = threadIdx.x;

    if (t < CH_) {
        const int kk = ch * CH_ + t;
        sp[t]  = g_perm[bh][kk] * HF_;
        sw0[t] = g_eads[bh][kk];
        sw1[t] = g_e1ds[bh][kk];
    }
    __syncthreads();
    if (t >= 65) return;

    const float* __restrict__ whb = g_Wh + (size_t)b * S_ * HF_ + h * F_ + t;
    const bool feat = (t < 64);
    float s0 = 0.f, s1 = 0.f;
#pragma unroll
    for (int k = 0; k < CH_; k++) {
        const float v = feat ? __ldg(whb + sp[k]) : 1.f;
        s0 += sw0[k] * v;
        s1 += sw1[k] * v;
    }
    g_csum0[bh][ch][t] = s0;
    g_csum1[bh][ch][t] = s1;
}

// ---------------------------------------------------------------------------
// K3b-C: materialize Q0/Q1; each block derives its own chunk offset.
// ---------------------------------------------------------------------------
__global__ void __launch_bounds__(96) scanC_kernel()
{
    __shared__ int   sp[CH_];
    __shared__ float sw0[CH_], sw1[CH_];
    const int bh = blockIdx.x;
    const int ch = blockIdx.y;
    const int b = bh >> 3, h = bh & 7;
    const int t = threadIdx.x;

    if (t < CH_) {
        const int kk = ch * CH_ + t;
        sp[t]  = g_perm[bh][kk] * HF_;
        sw0[t] = g_eads[bh][kk];
        sw1[t] = g_e1ds[bh][kk];
    }
    __syncthreads();
    if (t >= 65) return;

    float off0 = 0.f, off1 = 0.f;
    for (int c2 = 0; c2 < ch; c2++) {
        off0 += g_csum0[bh][c2][t];
        off1 += g_csum1[bh][c2][t];
    }

    const float* __restrict__ whb = g_Wh + (size_t)b * S_ * HF_ + h * F_ + t;
    const bool feat = (t < 64);
    const int k0 = ch * CH_;
#pragma unroll
    for (int k = 0; k < CH_; k++) {
        g_Q0[bh][k0 + k][t] = off0;
        g_Q1[bh][k0 + k][t] = off1;
        const float v = feat ? __ldg(whb + sp[k]) : 1.f;
        off0 += sw0[k] * v;
        off1 += sw1[k] * v;
    }
    if (ch == NCH_ - 1) {
        g_Q0[bh][S_][t] = off0;
        g_Q1[bh][S_][t] = off1;
    }
}

// ---------------------------------------------------------------------------
// K4: epilogue. Binary search split point; combine prefix/suffix; normalize.
// ---------------------------------------------------------------------------
__global__ void __launch_bounds__(256) out_kernel(float* __restrict__ out)
{
    __shared__ float ds[S_];
    const int b = blockIdx.z, h = blockIdx.y;
    const int bh = b * H_ + h;
    const int t = threadIdx.x;

    for (int q = t; q < S_; q += 256) ds[q] = g_dsorted[bh][q];
    __syncthreads();

    const int c4 = t & 15;
    const int il = t >> 4;
    const int i  = blockIdx.x * 16 + il;

    float4 ip = g_ipack[bh * S_ + i];
    const float e1s = ip.y, eas = ip.z;
    const float thr = -ip.x;

    int lo = 0, hi = S_;
    while (lo < hi) {
        int mid = (lo + hi) >> 1;
        if (ds[mid] < thr) lo = mid + 1; else hi = mid;
    }

    const float* q0 = &g_Q0[bh][lo][0];
    const float* q1 = &g_Q1[bh][lo][0];
    const float* t1 = &g_Q1[bh][S_][0];

    float4 n4 = *(const float4*)(q0 + c4 * 4);
    float4 q4 = *(const float4*)(q1 + c4 * 4);
    float4 t4 = *(const float4*)(t1 + c4 * 4);
    const float zpos = t1[64] - q1[64];
    const float inv = 1.f / (eas * q0[64] + e1s * zpos);

    float4 o;
    o.x = (eas * n4.x + e1s * (t4.x - q4.x)) * inv;
    o.y = (eas * n4.y + e1s * (t4.y - q4.y)) * inv;
    o.z = (eas * n4.z + e1s * (t4.z - q4.z)) * inv;
    o.w = (eas * n4.w + e1s * (t4.w - q4.w)) * inv;
    *(float4*)(out + (size_t)(b * S_ + i) * HF_ + h * F_ + c4 * 4) = o;
}

// ---------------------------------------------------------------------------
extern "C" void kernel_launch(void* const* d_in, const int* in_sizes, int n_in,
                              void* d_out, int out_size)
{
    const float* X    = (const float*)d_in[0];
    const int*   mask = (const int*)  d_in[1];
    const float* W    = (const float*)d_in[2];
    const float* a    = (const float*)d_in[3];
    float*       out  = (float*)d_out;

    static bool attr_set = false;
    if (!attr_set) {
        cudaFuncSetAttribute(mma_gemm_kernel,
                             cudaFuncAttributeMaxDynamicSharedMemorySize, 2 * STG_);
        attr_set = true;
    }

    convX_kernel<<<(B_ * S_ * IN_) / (256 * 4), 256>>>(X);
    convW_kernel<<<dim3(IN_ / 32, HF_ / 32), 256>>>(W);
    mma_gemm_kernel<<<dim3((B_ * S_) / 128, HF_ / 128), 256, 2 * STG_>>>(mask, a);
    sort_kernel<<<BH_, 1024>>>();
    scanA_kernel<<<dim3(BH_, NCH_), 96>>>();
    scanC_kernel<<<dim3(BH_, NCH_), 96>>>();
    out_kernel<<<dim3(S_ / 16, H_, B_), 256>>>(out);
}

// round 14
// speedup vs baseline: 1.7653x; 1.1935x over previous
#include <cuda_runtime.h>
#include <cuda_bf16.h>
#include <cuda_fp16.h>
#include <cstdint>

#define B_   8
#define S_   1024
#define IN_  768
#define H_   8
#define F_   64
#define HF_  512
#define BH_  (B_ * H_)
#define ALPHA_ 0.2f
#define NCH_  32
#define CH_   32

// ---------------------------------------------------------------------------
// Device scratch (no allocations allowed)
// ---------------------------------------------------------------------------
__device__ float  g_Wh[(size_t)B_ * S_ * HF_];
__device__ __half g_Xh[(size_t)B_ * S_ * IN_];       // X as fp16 (single)
__device__ __half g_Wth[(size_t)HF_ * IN_];          // W^T [n][k] fp16 hi
__device__ __half g_Wtl[(size_t)HF_ * IN_];          // fp16 lo (residual)

__device__ float4 g_ipack[BH_ * S_];                 // (s, e^s, e^{as}, 0)
__device__ float4 g_jpack[BH_ * S_];                 // (d, m e^d, m e^{ad}, 0)

__device__ __align__(16) float g_Q0[BH_][S_ + 1][68];
__device__ __align__(16) float g_Q1[BH_][S_ + 1][68];

// ---------------------------------------------------------------------------
// PTX helpers (baseline sm_80+ features only: valid on family target sm_103)
// ---------------------------------------------------------------------------
__device__ __forceinline__ uint32_t smem_u32(const void* p) {
    uint32_t a;
    asm("{ .reg .u64 t; cvta.to.shared.u64 t, %1; cvt.u32.u64 %0, t; }"
        : "=r"(a) : "l"(p));
    return a;
}
__device__ __forceinline__ unsigned long long gmem_u64(const void* p) {
    unsigned long long a;
    asm("cvta.to.global.u64 %0, %1;" : "=l"(a) : "l"(p));
    return a;
}
#define CP_ASYNC16(s, g) \
    asm volatile("cp.async.cg.shared.global [%0], [%1], 16;" :: "r"(s), "l"(g) : "memory")
#define CP_COMMIT() asm volatile("cp.async.commit_group;" ::: "memory")
#define CP_WAIT0()  asm volatile("cp.async.wait_group 0;" ::: "memory")

#define LDX4(r, addr) \
    asm volatile("ldmatrix.sync.aligned.m8n8.x4.shared.b16 {%0,%1,%2,%3}, [%4];" \
                 : "=r"((r)[0]), "=r"((r)[1]), "=r"((r)[2]), "=r"((r)[3]) : "r"(addr))

#define MMA_F16(cc, a, b0, b1) \
    asm volatile("mma.sync.aligned.m16n8k16.row.col.f32.f16.f16.f32 " \
                 "{%0,%1,%2,%3}, {%4,%5,%6,%7}, {%8,%9}, {%0,%1,%2,%3};" \
                 : "+f"((cc)[0]), "+f"((cc)[1]), "+f"((cc)[2]), "+f"((cc)[3]) \
                 : "r"((a)[0]), "r"((a)[1]), "r"((a)[2]), "r"((a)[3]), "r"(b0), "r"(b1))

// ---------------------------------------------------------------------------
// K0: fused conversion. Blocks [0,6144): X -> fp16. Blocks [6144,6528):
// transpose+split W -> Wt hi/lo fp16.
// ---------------------------------------------------------------------------
#define NXBLK_ ((B_ * S_ * IN_) / (256 * 4))   // 6144
#define NWBLK_ ((IN_ / 32) * (HF_ / 32))       // 384

__global__ void __launch_bounds__(256) conv_kernel(const float* __restrict__ X,
                                                   const float* __restrict__ W)
{
    __shared__ float tile[32][33];
    if (blockIdx.x < NXBLK_) {
        const size_t i = ((size_t)blockIdx.x * 256 + threadIdx.x) * 4;
        float4 v = *(const float4*)(X + i);
        *(__half2*)(g_Xh + i)     = __halves2half2(__float2half(v.x), __float2half(v.y));
        *(__half2*)(g_Xh + i + 2) = __halves2half2(__float2half(v.z), __float2half(v.w));
    } else {
        const int id = blockIdx.x - NXBLK_;
        const int kb = (id % (IN_ / 32)) * 32;
        const int nb = (id / (IN_ / 32)) * 32;
        const int tx = threadIdx.x & 31, ty = threadIdx.x >> 5;
#pragma unroll
        for (int r = ty; r < 32; r += 8)
            tile[r][tx] = W[(size_t)(kb + r) * HF_ + nb + tx];
        __syncthreads();
#pragma unroll
        for (int r = ty; r < 32; r += 8) {
            const float x = tile[tx][r];
            const __half hh = __float2half(x);
            g_Wth[(size_t)(nb + r) * IN_ + kb + tx] = hh;
            g_Wtl[(size_t)(nb + r) * IN_ + kb + tx] = __float2half(x - __half2float(hh));
        }
    }
}

// ---------------------------------------------------------------------------
// K1: fp16 2-product HMMA GEMM: Wh = X*Whi + X*Wlo, fp32 accum.
// CTA 128x128, 8 warps, BK=32, double-buffered cp.async, fused srcdst
// epilogue. Stage: A(fp16 X) | Bhi | Blo, 128 rows x 64B each, stride 80B.
// ---------------------------------------------------------------------------
#define STG_    30720
#define BHI_    10240
#define BLO_    20480
#define NSTAGE_ (IN_ / 32)   // 24

__global__ void __launch_bounds__(256, 2) mma_gemm_kernel(const int* __restrict__ mask,
                                                          const float* __restrict__ avec)
{
    extern __shared__ __align__(16) char smem[];
    __shared__ float s_asrc[64], s_adst[64];

    const int t = threadIdx.x;
    const int wid = t >> 5;
    const int lane = t & 31;
    const int warp_m = wid >> 1;
    const int warp_n = wid & 1;
    const int i0 = blockIdx.x * 128;
    const int f0 = blockIdx.y * 128;
    const uint32_t sb0 = smem_u32(smem);

    if (t < 64)       s_asrc[t]      = avec[t];
    else if (t < 128) s_adst[t - 64] = avec[t];

    float acc[2][8][4];
#pragma unroll
    for (int mt = 0; mt < 2; mt++)
#pragma unroll
        for (int nt = 0; nt < 8; nt++)
#pragma unroll
            for (int q = 0; q < 4; q++) acc[mt][nt][q] = 0.f;

    auto load_stage = [&](int ch, int s) {
        const uint32_t st = sb0 + s * STG_;
        const int k0 = ch * 32;
#pragma unroll
        for (int p = t; p < 512; p += 256) {
            const int row = p >> 2, q = p & 3;
            CP_ASYNC16(st + row * 80 + q * 16,
                       gmem_u64(g_Xh + (size_t)(i0 + row) * IN_ + k0 + q * 8));
        }
#pragma unroll
        for (int p = t; p < 512; p += 256) {
            const int row = p >> 2, q = p & 3;
            const uint32_t so = st + BHI_ + row * 80 + q * 16;
            const size_t gb = (size_t)(f0 + row) * IN_ + k0 + q * 8;
            CP_ASYNC16(so,                 gmem_u64(g_Wth + gb));
            CP_ASYNC16(so + (BLO_ - BHI_), gmem_u64(g_Wtl + gb));
        }
        CP_COMMIT();
    };

    load_stage(0, 0);

    const uint32_t a_lane_off = (lane & 15) * 80 + (lane >> 4) * 16;

    for (int ch = 0; ch < NSTAGE_; ch++) {
        CP_WAIT0();
        __syncthreads();
        if (ch + 1 < NSTAGE_) load_stage(ch + 1, (ch + 1) & 1);

        const uint32_t st = sb0 + (ch & 1) * STG_;
#pragma unroll
        for (int kt = 0; kt < 2; kt++) {
            uint32_t af[2][4];
#pragma unroll
            for (int mt = 0; mt < 2; mt++)
                LDX4(af[mt], st + (warp_m * 32 + mt * 16) * 80 + kt * 32 + a_lane_off);
#pragma unroll
            for (int nt = 0; nt < 4; nt++) {
                uint32_t bhf[4], blf[4];
                const uint32_t ba = st + BHI_ + (warp_n * 64 + nt * 16) * 80
                                  + kt * 32 + a_lane_off;
                LDX4(bhf, ba);
                LDX4(blf, ba + (BLO_ - BHI_));
#pragma unroll
                for (int mt = 0; mt < 2; mt++) {
                    MMA_F16(acc[mt][nt * 2],     af[mt], bhf[0], bhf[2]);
                    MMA_F16(acc[mt][nt * 2],     af[mt], blf[0], blf[2]);
                    MMA_F16(acc[mt][nt * 2 + 1], af[mt], bhf[1], bhf[3]);
                    MMA_F16(acc[mt][nt * 2 + 1], af[mt], blf[1], blf[3]);
                }
            }
        }
        __syncthreads();
    }

    // ---- epilogue 1: store Wh ----
#pragma unroll
    for (int mt = 0; mt < 2; mt++) {
        const int r0 = i0 + warp_m * 32 + mt * 16 + (lane >> 2);
#pragma unroll
        for (int nt = 0; nt < 8; nt++) {
            const int c = f0 + warp_n * 64 + nt * 8 + (lane & 3) * 2;
            *(float2*)(g_Wh + (size_t)r0 * HF_ + c) =
                make_float2(acc[mt][nt][0], acc[mt][nt][1]);
            *(float2*)(g_Wh + (size_t)(r0 + 8) * HF_ + c) =
                make_float2(acc[mt][nt][2], acc[mt][nt][3]);
        }
    }

    // ---- epilogue 2 (fused srcdst): warp tile = one full head ----
    const int h = blockIdx.y * 2 + warp_n;
    const int lq = lane & 3;
    float sp[4], dp[4];
#pragma unroll
    for (int mt = 0; mt < 2; mt++)
#pragma unroll
        for (int hf = 0; hf < 2; hf++) {
            float s = 0.f, d = 0.f;
#pragma unroll
            for (int nt = 0; nt < 8; nt++) {
                const int fi = nt * 8 + lq * 2;
                const float c0 = acc[mt][nt][hf * 2], c1 = acc[mt][nt][hf * 2 + 1];
                s += c0 * s_asrc[fi] + c1 * s_asrc[fi + 1];
                d += c0 * s_adst[fi] + c1 * s_adst[fi + 1];
            }
            sp[mt * 2 + hf] = s;
            dp[mt * 2 + hf] = d;
        }
#pragma unroll
    for (int q = 0; q < 4; q++) {
        sp[q] += __shfl_xor_sync(0xffffffffu, sp[q], 1);
        sp[q] += __shfl_xor_sync(0xffffffffu, sp[q], 2);
        dp[q] += __shfl_xor_sync(0xffffffffu, dp[q], 1);
        dp[q] += __shfl_xor_sync(0xffffffffu, dp[q], 2);
    }
    if (lq == 0) {
#pragma unroll
        for (int q = 0; q < 4; q++) {
            const int mt = q >> 1, hf = q & 1;
            const int row = i0 + warp_m * 32 + mt * 16 + hf * 8 + (lane >> 2);
            const int b = row >> 10, i = row & 1023;
            const int idx = (b * H_ + h) * S_ + i;
            const float s = sp[q], d = dp[q];
            g_ipack[idx] = make_float4(s, expf(s), expf(ALPHA_ * s), 0.f);
            const float m = mask[row] ? 1.f : 0.f;
            g_jpack[idx] = make_float4(d, m * expf(d), m * expf(ALPHA_ * d), 0.f);
        }
    }
}

// ---------------------------------------------------------------------------
// K2: fused tail. One block per (b,h), 1024 threads:
//   sort -> chunk sums (warp/chunk) -> in-smem chunk scan -> Q materialize
//   -> output epilogue. Q arrays stay global (block-local, L2-hot).
// ---------------------------------------------------------------------------
__device__ __forceinline__ unsigned long long
bitonic_warp_tail(unsigned long long v, int t, int k, int jmax)
{
    const bool up = ((t & k) == 0);
#pragma unroll
    for (int j = 16; j > 0; j >>= 1) {
        if (j > jmax) continue;
        const unsigned long long p = __shfl_xor_sync(0xffffffffu, v, j);
        const bool lower = ((t & j) == 0);
        const bool keep_min = (lower == up);
        v = keep_min ? (v < p ? v : p) : (v > p ? v : p);
    }
    return v;
}

__global__ void __launch_bounds__(1024) tail_kernel(float* __restrict__ out)
{
    __shared__ unsigned long long sv[S_];
    __shared__ float ds[S_], se0[S_], se1[S_];
    __shared__ int   spm[S_];
    __shared__ float cs0[NCH_][66], cs1[NCH_][66];

    const int bh = blockIdx.x;
    const int b = bh >> 3, h = bh & 7;
    const int t = threadIdx.x;

    // ---- sort (hybrid bitonic on packed u64) ----
    unsigned long long v;
    {
        const uint32_t u = __float_as_uint(g_jpack[bh * S_ + t].x);
        const uint32_t s = (u & 0x80000000u) ? ~u : (u ^ 0x80000000u);
        v = ((unsigned long long)s << 32) | (unsigned)t;
    }
#pragma unroll
    for (int k = 2; k <= 32; k <<= 1)
        v = bitonic_warp_tail(v, t, k, k >> 1);
    sv[t] = v;
    __syncthreads();
    for (int k = 64; k <= S_; k <<= 1) {
        for (int j = k >> 1; j >= 32; j >>= 1) {
            const int ixj = t ^ j;
            if (ixj > t) {
                const bool up = ((t & k) == 0);
                const unsigned long long a = sv[t], b2 = sv[ixj];
                if (up ? (a > b2) : (a < b2)) { sv[t] = b2; sv[ixj] = a; }
            }
            __syncthreads();
        }
        v = sv[t];
        v = bitonic_warp_tail(v, t, k, 16);
        sv[t] = v;
        __syncthreads();
    }

    {
        const int p = (int)(v & 0xFFFFFFFFu);
        const uint32_t s = (uint32_t)(v >> 32);
        const uint32_t u = (s & 0x80000000u) ? (s ^ 0x80000000u) : ~s;
        float4 jp = g_jpack[bh * S_ + p];
        ds[t]  = __uint_as_float(u);
        spm[t] = p;
        se1[t] = jp.y;    // m*e^d
        se0[t] = jp.z;    // m*e^{ad}
    }
    __syncthreads();

    const int w = t >> 5, lane = t & 31;
    const float* __restrict__ whb = g_Wh + (size_t)b * S_ * HF_ + h * F_;

    // ---- phase A: chunk partial sums (warp w = chunk w) ----
    {
        float s0a = 0.f, s0b = 0.f, s1a = 0.f, s1b = 0.f, z0 = 0.f, z1 = 0.f;
#pragma unroll 4
        for (int k = 0; k < CH_; k++) {
            const int kk = w * CH_ + k;
            const float* r = whb + (size_t)spm[kk] * HF_;
            const float w0 = se0[kk], w1 = se1[kk];
            const float va = __ldg(r + lane), vb = __ldg(r + lane + 32);
            s0a += w0 * va; s0b += w0 * vb;
            s1a += w1 * va; s1b += w1 * vb;
            z0 += w0; z1 += w1;
        }
        cs0[w][lane] = s0a; cs0[w][lane + 32] = s0b;
        cs1[w][lane] = s1a; cs1[w][lane + 32] = s1b;
        if (lane == 0) { cs0[w][64] = z0; cs1[w][64] = z1; }
    }
    __syncthreads();

    // ---- phase B: exclusive scan of the 32 chunk sums, per column ----
    if (t < 130) {
        float* col = (t < 65) ? &cs0[0][t] : &cs1[0][t - 65];
        float a = 0.f;
#pragma unroll
        for (int ch = 0; ch < NCH_; ch++) {
            const float x = col[ch * 66];
            col[ch * 66] = a;
            a += x;
        }
    }
    __syncthreads();

    // ---- phase C: materialize Q0/Q1 ----
    {
        float o0a = cs0[w][lane], o0b = cs0[w][lane + 32];
        float o1a = cs1[w][lane], o1b = cs1[w][lane + 32];
        float oz0 = cs0[w][64],   oz1 = cs1[w][64];
#pragma unroll 4
        for (int k = 0; k < CH_; k++) {
            const int kk = w * CH_ + k;
            float* q0 = &g_Q0[bh][kk][0];
            float* q1 = &g_Q1[bh][kk][0];
            q0[lane] = o0a; q0[lane + 32] = o0b;
            q1[lane] = o1a; q1[lane + 32] = o1b;
            if (lane == 0) { q0[64] = oz0; q1[64] = oz1; }
            const float* r = whb + (size_t)spm[kk] * HF_;
            const float w0 = se0[kk], w1 = se1[kk];
            const float va = __ldg(r + lane), vb = __ldg(r + lane + 32);
            o0a += w0 * va; o0b += w0 * vb;
            o1a += w1 * va; o1b += w1 * vb;
            oz0 += w0; oz1 += w1;
        }
        if (w == NCH_ - 1) {
            float* q0 = &g_Q0[bh][S_][0];
            float* q1 = &g_Q1[bh][S_][0];
            q0[lane] = o0a; q0[lane + 32] = o0b;
            q1[lane] = o1a; q1[lane + 32] = o1b;
            if (lane == 0) { q0[64] = oz0; q1[64] = oz1; }
        }
    }
    __syncthreads();   // global writes by block visible to block

    // ---- phase D: output epilogue ----
    const int c4 = t & 15;
    const int il = t >> 4;
    const float* t1r = &g_Q1[bh][S_][0];
    for (int rep = 0; rep < 16; rep++) {
        const int i = rep * 64 + il;
        float4 ip = g_ipack[bh * S_ + i];
        const float e1s = ip.y, eas = ip.z;
        const float thr = -ip.x;

        int lo = 0, hi = S_;
        while (lo < hi) {
            const int mid = (lo + hi) >> 1;
            if (ds[mid] < thr) lo = mid + 1; else hi = mid;
        }

        const float* q0 = &g_Q0[bh][lo][0];
        const float* q1 = &g_Q1[bh][lo][0];
        float4 n4 = *(const float4*)(q0 + c4 * 4);
        float4 q4 = *(const float4*)(q1 + c4 * 4);
        float4 t4 = *(const float4*)(t1r + c4 * 4);
        const float zpos = t1r[64] - q1[64];
        const float inv = 1.f / (eas * q0[64] + e1s * zpos);

        float4 o;
        o.x = (eas * n4.x + e1s * (t4.x - q4.x)) * inv;
        o.y = (eas * n4.y + e1s * (t4.y - q4.y)) * inv;
        o.z = (eas * n4.z + e1s * (t4.z - q4.z)) * inv;
        o.w = (eas * n4.w + e1s * (t4.w - q4.w)) * inv;
        *(float4*)(out + (size_t)(b * S_ + i) * HF_ + h * F_ + c4 * 4) = o;
    }
}

// ---------------------------------------------------------------------------
extern "C" void kernel_launch(void* const* d_in, const int* in_sizes, int n_in,
                              void* d_out, int out_size)
{
    const float* X    = (const float*)d_in[0];
    const int*   mask = (const int*)  d_in[1];
    const float* W    = (const float*)d_in[2];
    const float* a    = (const float*)d_in[3];
    float*       out  = (float*)d_out;

    static bool attr_set = false;
    if (!attr_set) {
        cudaFuncSetAttribute(mma_gemm_kernel,
                             cudaFuncAttributeMaxDynamicSharedMemorySize, 2 * STG_);
        attr_set = true;
    }

    conv_kernel<<<NXBLK_ + NWBLK_, 256>>>(X, W);
    mma_gemm_kernel<<<dim3((B_ * S_) / 128, HF_ / 128), 256, 2 * STG_>>>(mask, a);
    tail_kernel<<<BH_, 1024>>>(out);
}

// round 15
// speedup vs baseline: 2.1264x; 1.2046x over previous
#include <cuda_runtime.h>
#include <cuda_bf16.h>
#include <cuda_fp16.h>
#include <cstdint>

#define B_   8
#define S_   1024
#define IN_  768
#define H_   8
#define F_   64
#define HF_  512
#define BH_  (B_ * H_)
#define ALPHA_ 0.2f
#define NCH_  32
#define CH_   32

// ---------------------------------------------------------------------------
// Device scratch (no allocations allowed)
// ---------------------------------------------------------------------------
__device__ float  g_Wh[(size_t)B_ * S_ * HF_];
__device__ __half g_Xh[(size_t)B_ * S_ * IN_];       // X as fp16
__device__ __half g_Wth[(size_t)HF_ * IN_];          // W^T [n][k] fp16

__device__ float4 g_ipack[BH_ * S_];                 // (s, e^s, e^{as}, 0)
__device__ float4 g_jpack[BH_ * S_];                 // (d, m e^d, m e^{ad}, 0)

__device__ __align__(16) float g_Q0[BH_][S_ + 1][68];
__device__ __align__(16) float g_Q1[BH_][S_ + 1][68];

// ---------------------------------------------------------------------------
// PTX helpers (baseline sm_80+ features only: valid on family target sm_103)
// ---------------------------------------------------------------------------
__device__ __forceinline__ uint32_t smem_u32(const void* p) {
    uint32_t a;
    asm("{ .reg .u64 t; cvta.to.shared.u64 t, %1; cvt.u32.u64 %0, t; }"
        : "=r"(a) : "l"(p));
    return a;
}
__device__ __forceinline__ unsigned long long gmem_u64(const void* p) {
    unsigned long long a;
    asm("cvta.to.global.u64 %0, %1;" : "=l"(a) : "l"(p));
    return a;
}
#define CP_ASYNC16(s, g) \
    asm volatile("cp.async.cg.shared.global [%0], [%1], 16;" :: "r"(s), "l"(g) : "memory")
#define CP_COMMIT() asm volatile("cp.async.commit_group;" ::: "memory")
#define CP_WAIT1()  asm volatile("cp.async.wait_group 1;" ::: "memory")
#define CP_WAIT0()  asm volatile("cp.async.wait_group 0;" ::: "memory")

#define LDX4(r, addr) \
    asm volatile("ldmatrix.sync.aligned.m8n8.x4.shared.b16 {%0,%1,%2,%3}, [%4];" \
                 : "=r"((r)[0]), "=r"((r)[1]), "=r"((r)[2]), "=r"((r)[3]) : "r"(addr))

#define MMA_F16(cc, a, b0, b1) \
    asm volatile("mma.sync.aligned.m16n8k16.row.col.f32.f16.f16.f32 " \
                 "{%0,%1,%2,%3}, {%4,%5,%6,%7}, {%8,%9}, {%0,%1,%2,%3};" \
                 : "+f"((cc)[0]), "+f"((cc)[1]), "+f"((cc)[2]), "+f"((cc)[3]) \
                 : "r"((a)[0]), "r"((a)[1]), "r"((a)[2]), "r"((a)[3]), "r"(b0), "r"(b1))

// ---------------------------------------------------------------------------
// K0: fused conversion. Blocks [0,6144): X -> fp16. Rest: transpose W -> fp16.
// ---------------------------------------------------------------------------
#define NXBLK_ ((B_ * S_ * IN_) / (256 * 4))   // 6144
#define NWBLK_ ((IN_ / 32) * (HF_ / 32))       // 384

__global__ void __launch_bounds__(256) conv_kernel(const float* __restrict__ X,
                                                   const float* __restrict__ W)
{
    __shared__ float tile[32][33];
    if (blockIdx.x < NXBLK_) {
        const size_t i = ((size_t)blockIdx.x * 256 + threadIdx.x) * 4;
        float4 v = *(const float4*)(X + i);
        *(__half2*)(g_Xh + i)     = __halves2half2(__float2half(v.x), __float2half(v.y));
        *(__half2*)(g_Xh + i + 2) = __halves2half2(__float2half(v.z), __float2half(v.w));
    } else {
        const int id = blockIdx.x - NXBLK_;
        const int kb = (id % (IN_ / 32)) * 32;
        const int nb = (id / (IN_ / 32)) * 32;
        const int tx = threadIdx.x & 31, ty = threadIdx.x >> 5;
#pragma unroll
        for (int r = ty; r < 32; r += 8)
            tile[r][tx] = W[(size_t)(kb + r) * HF_ + nb + tx];
        __syncthreads();
#pragma unroll
        for (int r = ty; r < 32; r += 8)
            g_Wth[(size_t)(nb + r) * IN_ + kb + tx] = __float2half(tile[tx][r]);
    }
}

// ---------------------------------------------------------------------------
// K1: single-product fp16 HMMA GEMM: Wh = fp16(X)*fp16(W), fp32 accum.
// CTA 128x128, 8 warps, BK=32, 3-stage cp.async pipeline, fused srcdst
// epilogue. Stage: A | B, 128 rows x 64B each, stride 80B. 20KB/stage.
// ---------------------------------------------------------------------------
#define STG_    20480
#define BOFF_   10240
#define NSTAGE_ (IN_ / 32)   // 24

__global__ void __launch_bounds__(256, 2) mma_gemm_kernel(const int* __restrict__ mask,
                                                          const float* __restrict__ avec)
{
    extern __shared__ __align__(16) char smem[];
    __shared__ float s_asrc[64], s_adst[64];

    const int t = threadIdx.x;
    const int wid = t >> 5;
    const int lane = t & 31;
    const int warp_m = wid >> 1;
    const int warp_n = wid & 1;
    const int i0 = blockIdx.x * 128;
    const int f0 = blockIdx.y * 128;
    const uint32_t sb0 = smem_u32(smem);

    if (t < 64)       s_asrc[t]      = avec[t];
    else if (t < 128) s_adst[t - 64] = avec[t];

    float acc[2][8][4];
#pragma unroll
    for (int mt = 0; mt < 2; mt++)
#pragma unroll
        for (int nt = 0; nt < 8; nt++)
#pragma unroll
            for (int q = 0; q < 4; q++) acc[mt][nt][q] = 0.f;

    auto load_stage = [&](int ch, int s) {
        const uint32_t st = sb0 + s * STG_;
        const int k0 = ch * 32;
#pragma unroll
        for (int p = t; p < 512; p += 256) {
            const int row = p >> 2, q = p & 3;
            const uint32_t so = st + row * 80 + q * 16;
            CP_ASYNC16(so, gmem_u64(g_Xh + (size_t)(i0 + row) * IN_ + k0 + q * 8));
            CP_ASYNC16(so + BOFF_,
                       gmem_u64(g_Wth + (size_t)(f0 + row) * IN_ + k0 + q * 8));
        }
        CP_COMMIT();
    };

    load_stage(0, 0);
    load_stage(1, 1);

    const uint32_t a_lane_off = (lane & 15) * 80 + (lane >> 4) * 16;

    for (int ch = 0; ch < NSTAGE_; ch++) {
        CP_WAIT1();
        __syncthreads();
        if (ch + 2 < NSTAGE_) load_stage(ch + 2, (ch + 2) % 3);

        const uint32_t st = sb0 + (ch % 3) * STG_;
#pragma unroll
        for (int kt = 0; kt < 2; kt++) {
            uint32_t af[2][4];
#pragma unroll
            for (int mt = 0; mt < 2; mt++)
                LDX4(af[mt], st + (warp_m * 32 + mt * 16) * 80 + kt * 32 + a_lane_off);
#pragma unroll
            for (int nt = 0; nt < 4; nt++) {
                uint32_t bf[4];
                LDX4(bf, st + BOFF_ + (warp_n * 64 + nt * 16) * 80
                         + kt * 32 + a_lane_off);
#pragma unroll
                for (int mt = 0; mt < 2; mt++) {
                    MMA_F16(acc[mt][nt * 2],     af[mt], bf[0], bf[2]);
                    MMA_F16(acc[mt][nt * 2 + 1], af[mt], bf[1], bf[3]);
                }
            }
        }
        __syncthreads();
    }

    // ---- epilogue 1: store Wh ----
#pragma unroll
    for (int mt = 0; mt < 2; mt++) {
        const int r0 = i0 + warp_m * 32 + mt * 16 + (lane >> 2);
#pragma unroll
        for (int nt = 0; nt < 8; nt++) {
            const int c = f0 + warp_n * 64 + nt * 8 + (lane & 3) * 2;
            *(float2*)(g_Wh + (size_t)r0 * HF_ + c) =
                make_float2(acc[mt][nt][0], acc[mt][nt][1]);
            *(float2*)(g_Wh + (size_t)(r0 + 8) * HF_ + c) =
                make_float2(acc[mt][nt][2], acc[mt][nt][3]);
        }
    }

    // ---- epilogue 2 (fused srcdst): warp tile = one full head ----
    const int h = blockIdx.y * 2 + warp_n;
    const int lq = lane & 3;
    float sp[4], dp[4];
#pragma unroll
    for (int mt = 0; mt < 2; mt++)
#pragma unroll
        for (int hf = 0; hf < 2; hf++) {
            float s = 0.f, d = 0.f;
#pragma unroll
            for (int nt = 0; nt < 8; nt++) {
                const int fi = nt * 8 + lq * 2;
                const float c0 = acc[mt][nt][hf * 2], c1 = acc[mt][nt][hf * 2 + 1];
                s += c0 * s_asrc[fi] + c1 * s_asrc[fi + 1];
                d += c0 * s_adst[fi] + c1 * s_adst[fi + 1];
            }
            sp[mt * 2 + hf] = s;
            dp[mt * 2 + hf] = d;
        }
#pragma unroll
    for (int q = 0; q < 4; q++) {
        sp[q] += __shfl_xor_sync(0xffffffffu, sp[q], 1);
        sp[q] += __shfl_xor_sync(0xffffffffu, sp[q], 2);
        dp[q] += __shfl_xor_sync(0xffffffffu, dp[q], 1);
        dp[q] += __shfl_xor_sync(0xffffffffu, dp[q], 2);
    }
    if (lq == 0) {
#pragma unroll
        for (int q = 0; q < 4; q++) {
            const int mt = q >> 1, hf = q & 1;
            const int row = i0 + warp_m * 32 + mt * 16 + hf * 8 + (lane >> 2);
            const int b = row >> 10, i = row & 1023;
            const int idx = (b * H_ + h) * S_ + i;
            const float s = sp[q], d = dp[q];
            g_ipack[idx] = make_float4(s, expf(s), expf(ALPHA_ * s), 0.f);
            const float m = mask[row] ? 1.f : 0.f;
            g_jpack[idx] = make_float4(d, m * expf(d), m * expf(ALPHA_ * d), 0.f);
        }
    }
}

// ---------------------------------------------------------------------------
// K2: fused tail. One block per (b,h), 1024 threads:
//   sort -> chunk sums -> in-smem chunk scan -> Q materialize -> output.
// ---------------------------------------------------------------------------
__device__ __forceinline__ unsigned long long
bitonic_warp_tail(unsigned long long v, int t, int k, int jmax)
{
    const bool up = ((t & k) == 0);
#pragma unroll
    for (int j = 16; j > 0; j >>= 1) {
        if (j > jmax) continue;
        const unsigned long long p = __shfl_xor_sync(0xffffffffu, v, j);
        const bool lower = ((t & j) == 0);
        const bool keep_min = (lower == up);
        v = keep_min ? (v < p ? v : p) : (v > p ? v : p);
    }
    return v;
}

__global__ void __launch_bounds__(1024) tail_kernel(float* __restrict__ out)
{
    __shared__ unsigned long long sv[S_];
    __shared__ float ds[S_], se0[S_], se1[S_];
    __shared__ int   spm[S_];
    __shared__ float cs0[NCH_][66], cs1[NCH_][66];

    const int bh = blockIdx.x;
    const int b = bh >> 3, h = bh & 7;
    const int t = threadIdx.x;

    // ---- sort (hybrid bitonic on packed u64) ----
    unsigned long long v;
    {
        const uint32_t u = __float_as_uint(g_jpack[bh * S_ + t].x);
        const uint32_t s = (u & 0x80000000u) ? ~u : (u ^ 0x80000000u);
        v = ((unsigned long long)s << 32) | (unsigned)t;
    }
#pragma unroll
    for (int k = 2; k <= 32; k <<= 1)
        v = bitonic_warp_tail(v, t, k, k >> 1);
    sv[t] = v;
    __syncthreads();
    for (int k = 64; k <= S_; k <<= 1) {
        for (int j = k >> 1; j >= 32; j >>= 1) {
            const int ixj = t ^ j;
            if (ixj > t) {
                const bool up = ((t & k) == 0);
                const unsigned long long a = sv[t], b2 = sv[ixj];
                if (up ? (a > b2) : (a < b2)) { sv[t] = b2; sv[ixj] = a; }
            }
            __syncthreads();
        }
        v = sv[t];
        v = bitonic_warp_tail(v, t, k, 16);
        sv[t] = v;
        __syncthreads();
    }

    {
        const int p = (int)(v & 0xFFFFFFFFu);
        const uint32_t s = (uint32_t)(v >> 32);
        const uint32_t u = (s & 0x80000000u) ? (s ^ 0x80000000u) : ~s;
        float4 jp = g_jpack[bh * S_ + p];
        ds[t]  = __uint_as_float(u);
        spm[t] = p;
        se1[t] = jp.y;    // m*e^d
        se0[t] = jp.z;    // m*e^{ad}
    }
    __syncthreads();

    const int w = t >> 5, lane = t & 31;
    const float* __restrict__ whb = g_Wh + (size_t)b * S_ * HF_ + h * F_;

    // ---- phase A: chunk partial sums (warp w = chunk w) ----
    {
        float s0a = 0.f, s0b = 0.f, s1a = 0.f, s1b = 0.f, z0 = 0.f, z1 = 0.f;
#pragma unroll 4
        for (int k = 0; k < CH_; k++) {
            const int kk = w * CH_ + k;
            const float* r = whb + (size_t)spm[kk] * HF_;
            const float w0 = se0[kk], w1 = se1[kk];
            const float va = __ldg(r + lane), vb = __ldg(r + lane + 32);
            s0a += w0 * va; s0b += w0 * vb;
            s1a += w1 * va; s1b += w1 * vb;
            z0 += w0; z1 += w1;
        }
        cs0[w][lane] = s0a; cs0[w][lane + 32] = s0b;
        cs1[w][lane] = s1a; cs1[w][lane + 32] = s1b;
        if (lane == 0) { cs0[w][64] = z0; cs1[w][64] = z1; }
    }
    __syncthreads();

    // ---- phase B: exclusive scan of the 32 chunk sums, per column ----
    if (t < 130) {
        float* col = (t < 65) ? &cs0[0][t] : &cs1[0][t - 65];
        float a = 0.f;
#pragma unroll
        for (int ch = 0; ch < NCH_; ch++) {
            const float x = col[ch * 66];
            col[ch * 66] = a;
            a += x;
        }
    }
    __syncthreads();

    // ---- phase C: materialize Q0/Q1 ----
    {
        float o0a = cs0[w][lane], o0b = cs0[w][lane + 32];
        float o1a = cs1[w][lane], o1b = cs1[w][lane + 32];
        float oz0 = cs0[w][64],   oz1 = cs1[w][64];
#pragma unroll 4
        for (int k = 0; k < CH_; k++) {
            const int kk = w * CH_ + k;
            float* q0 = &g_Q0[bh][kk][0];
            float* q1 = &g_Q1[bh][kk][0];
            q0[lane] = o0a; q0[lane + 32] = o0b;
            q1[lane] = o1a; q1[lane + 32] = o1b;
            if (lane == 0) { q0[64] = oz0; q1[64] = oz1; }
            const float* r = whb + (size_t)spm[kk] * HF_;
            const float w0 = se0[kk], w1 = se1[kk];
            const float va = __ldg(r + lane), vb = __ldg(r + lane + 32);
            o0a += w0 * va; o0b += w0 * vb;
            o1a += w1 * va; o1b += w1 * vb;
            oz0 += w0; oz1 += w1;
        }
        if (w == NCH_ - 1) {
            float* q0 = &g_Q0[bh][S_][0];
            float* q1 = &g_Q1[bh][S_][0];
            q0[lane] = o0a; q0[lane + 32] = o0b;
            q1[lane] = o1a; q1[lane + 32] = o1b;
            if (lane == 0) { q0[64] = oz0; q1[64] = oz1; }
        }
    }
    __syncthreads();

    // ---- phase D: output epilogue ----
    const int c4 = t & 15;
    const int il = t >> 4;
    const float* t1r = &g_Q1[bh][S_][0];
    for (int rep = 0; rep < 16; rep++) {
        const int i = rep * 64 + il;
        float4 ip = g_ipack[bh * S_ + i];
        const float e1s = ip.y, eas = ip.z;
        const float thr = -ip.x;

        int lo = 0, hi = S_;
        while (lo < hi) {
            const int mid = (lo + hi) >> 1;
            if (ds[mid] < thr) lo = mid + 1; else hi = mid;
        }

        const float* q0 = &g_Q0[bh][lo][0];
        const float* q1 = &g_Q1[bh][lo][0];
        float4 n4 = *(const float4*)(q0 + c4 * 4);
        float4 q4 = *(const float4*)(q1 + c4 * 4);
        float4 t4 = *(const float4*)(t1r + c4 * 4);
        const float zpos = t1r[64] - q1[64];
        const float inv = 1.f / (eas * q0[64] + e1s * zpos);

        float4 o;
        o.x = (eas * n4.x + e1s * (t4.x - q4.x)) * inv;
        o.y = (eas * n4.y + e1s * (t4.y - q4.y)) * inv;
        o.z = (eas * n4.z + e1s * (t4.z - q4.z)) * inv;
        o.w = (eas * n4.w + e1s * (t4.w - q4.w)) * inv;
        *(float4*)(out + (size_t)(b * S_ + i) * HF_ + h * F_ + c4 * 4) = o;
    }
}

// ---------------------------------------------------------------------------
extern "C" void kernel_launch(void* const* d_in, const int* in_sizes, int n_in,
                              void* d_out, int out_size)
{
    const float* X    = (const float*)d_in[0];
    const int*   mask = (const int*)  d_in[1];
    const float* W    = (const float*)d_in[2];
    const float* a    = (const float*)d_in[3];
    float*       out  = (float*)d_out;

    static bool attr_set = false;
    if (!attr_set) {
        cudaFuncSetAttribute(mma_gemm_kernel,
                             cudaFuncAttributeMaxDynamicSharedMemorySize, 3 * STG_);
        attr_set = true;
    }

    conv_kernel<<<NXBLK_ + NWBLK_, 256>>>(X, W);
    mma_gemm_kernel<<<dim3((B_ * S_) / 128, HF_ / 128), 256, 3 * STG_>>>(mask, a);
    tail_kernel<<<BH_, 1024>>>(out);
}

// round 17
// speedup vs baseline: 2.4045x; 1.1308x over previous
#include <cuda_runtime.h>
#include <cuda_bf16.h>
#include <cuda_fp16.h>
#include <cstdint>

#define B_   8
#define S_   1024
#define IN_  768
#define H_   8
#define F_   64
#define HF_  512
#define BH_  (B_ * H_)
#define ALPHA_ 0.2f
#define NCH_  32
#define CH_   32

// ---------------------------------------------------------------------------
// Device scratch (no allocations allowed)
// ---------------------------------------------------------------------------
__device__ float  g_Wh[(size_t)B_ * S_ * HF_];
__device__ __half g_Xh[(size_t)B_ * S_ * IN_];       // X as fp16
__device__ __half g_Wth[(size_t)HF_ * IN_];          // W^T [n][k] fp16

__device__ float4 g_ipack[BH_ * S_];                 // (s, e^s, e^{as}, 0)
__device__ float4 g_jpack[BH_ * S_];                 // (d, m e^d, m e^{ad}, 0)

__device__ float  g_dsorted[BH_][S_];
__device__ int    g_perm[BH_][S_];
__device__ float  g_e1ds[BH_][S_];                   // m e^d   (sorted)
__device__ float  g_eads[BH_][S_];                   // m e^{ad}(sorted)

__device__ __align__(16) float g_Q0[BH_][S_ + 1][68];
__device__ __align__(16) float g_Q1[BH_][S_ + 1][68];

// ---------------------------------------------------------------------------
// PTX helpers (baseline sm_80+ features only: valid on family target sm_103)
// ---------------------------------------------------------------------------
__device__ __forceinline__ uint32_t smem_u32(const void* p) {
    uint32_t a;
    asm("{ .reg .u64 t; cvta.to.shared.u64 t, %1; cvt.u32.u64 %0, t; }"
        : "=r"(a) : "l"(p));
    return a;
}
__device__ __forceinline__ unsigned long long gmem_u64(const void* p) {
    unsigned long long a;
    asm("cvta.to.global.u64 %0, %1;" : "=l"(a) : "l"(p));
    return a;
}
__device__ __forceinline__ uint32_t pack_f2h2(float a, float b) {
    const uint32_t lo = (uint32_t)__half_as_ushort(__float2half(a));
    const uint32_t hi = (uint32_t)__half_as_ushort(__float2half(b));
    return lo | (hi << 16);
}
#define CP_ASYNC16(s, g) \
    asm volatile("cp.async.cg.shared.global [%0], [%1], 16;" :: "r"(s), "l"(g) : "memory")
#define CP_COMMIT() asm volatile("cp.async.commit_group;" ::: "memory")
#define CP_WAIT1()  asm volatile("cp.async.wait_group 1;" ::: "memory")

#define LDX4(r, addr) \
    asm volatile("ldmatrix.sync.aligned.m8n8.x4.shared.b16 {%0,%1,%2,%3}, [%4];" \
                 : "=r"((r)[0]), "=r"((r)[1]), "=r"((r)[2]), "=r"((r)[3]) : "r"(addr))

#define MMA_F16(cc, a, b0, b1) \
    asm volatile("mma.sync.aligned.m16n8k16.row.col.f32.f16.f16.f32 " \
                 "{%0,%1,%2,%3}, {%4,%5,%6,%7}, {%8,%9}, {%0,%1,%2,%3};" \
                 : "+f"((cc)[0]), "+f"((cc)[1]), "+f"((cc)[2]), "+f"((cc)[3]) \
                 : "r"((a)[0]), "r"((a)[1]), "r"((a)[2]), "r"((a)[3]), "r"(b0), "r"(b1))

// ---------------------------------------------------------------------------
// K0: fused conversion. X path: 8 elems/thread, single 16B store.
// ---------------------------------------------------------------------------
#define NXBLK_ ((B_ * S_ * IN_) / (256 * 8))   // 3072
#define NWBLK_ ((IN_ / 32) * (HF_ / 32))       // 384

__global__ void __launch_bounds__(256) conv_kernel(const float* __restrict__ X,
                                                   const float* __restrict__ W)
{
    __shared__ float tile[32][33];
    if (blockIdx.x < NXBLK_) {
        const size_t i = ((size_t)blockIdx.x * 256 + threadIdx.x) * 8;
        float4 v0 = *(const float4*)(X + i);
        float4 v1 = *(const float4*)(X + i + 4);
        uint4 o;
        o.x = pack_f2h2(v0.x, v0.y);
        o.y = pack_f2h2(v0.z, v0.w);
        o.z = pack_f2h2(v1.x, v1.y);
        o.w = pack_f2h2(v1.z, v1.w);
        *(uint4*)(g_Xh + i) = o;
    } else {
        const int id = blockIdx.x - NXBLK_;
        const int kb = (id % (IN_ / 32)) * 32;
        const int nb = (id / (IN_ / 32)) * 32;
        const int tx = threadIdx.x & 31, ty = threadIdx.x >> 5;
#pragma unroll
        for (int r = ty; r < 32; r += 8)
            tile[r][tx] = W[(size_t)(kb + r) * HF_ + nb + tx];
        __syncthreads();
#pragma unroll
        for (int r = ty; r < 32; r += 8)
            g_Wth[(size_t)(nb + r) * IN_ + kb + tx] = __float2half(tile[tx][r]);
    }
}

// ---------------------------------------------------------------------------
// K1: single-product fp16 HMMA GEMM (R15 best, unchanged).
// ---------------------------------------------------------------------------
#define STG_    20480
#define BOFF_   10240
#define NSTAGE_ (IN_ / 32)   // 24

__global__ void __launch_bounds__(256, 2) mma_gemm_kernel(const int* __restrict__ mask,
                                                          const float* __restrict__ avec)
{
    extern __shared__ __align__(16) char smem[];
    __shared__ float s_asrc[64], s_adst[64];

    const int t = threadIdx.x;
    const int wid = t >> 5;
    const int lane = t & 31;
    const int warp_m = wid >> 1;
    const int warp_n = wid & 1;
    const int i0 = blockIdx.x * 128;
    const int f0 = blockIdx.y * 128;
    const uint32_t sb0 = smem_u32(smem);

    if (t < 64)       s_asrc[t]      = avec[t];
    else if (t < 128) s_adst[t - 64] = avec[t];

    float acc[2][8][4];
#pragma unroll
    for (int mt = 0; mt < 2; mt++)
#pragma unroll
        for (int nt = 0; nt < 8; nt++)
#pragma unroll
            for (int q = 0; q < 4; q++) acc[mt][nt][q] = 0.f;

    auto load_stage = [&](int ch, int s) {
        const uint32_t st = sb0 + s * STG_;
        const int k0 = ch * 32;
#pragma unroll
        for (int p = t; p < 512; p += 256) {
            const int row = p >> 2, q = p & 3;
            const uint32_t so = st + row * 80 + q * 16;
            CP_ASYNC16(so, gmem_u64(g_Xh + (size_t)(i0 + row) * IN_ + k0 + q * 8));
            CP_ASYNC16(so + BOFF_,
                       gmem_u64(g_Wth + (size_t)(f0 + row) * IN_ + k0 + q * 8));
        }
        CP_COMMIT();
    };

    load_stage(0, 0);
    load_stage(1, 1);

    const uint32_t a_lane_off = (lane & 15) * 80 + (lane >> 4) * 16;

    for (int ch = 0; ch < NSTAGE_; ch++) {
        CP_WAIT1();
        __syncthreads();
        if (ch + 2 < NSTAGE_) load_stage(ch + 2, (ch + 2) % 3);

        const uint32_t st = sb0 + (ch % 3) * STG_;
#pragma unroll
        for (int kt = 0; kt < 2; kt++) {
            uint32_t af[2][4];
#pragma unroll
            for (int mt = 0; mt < 2; mt++)
                LDX4(af[mt], st + (warp_m * 32 + mt * 16) * 80 + kt * 32 + a_lane_off);
#pragma unroll
            for (int nt = 0; nt < 4; nt++) {
                uint32_t bf[4];
                LDX4(bf, st + BOFF_ + (warp_n * 64 + nt * 16) * 80
                         + kt * 32 + a_lane_off);
#pragma unroll
                for (int mt = 0; mt < 2; mt++) {
                    MMA_F16(acc[mt][nt * 2],     af[mt], bf[0], bf[2]);
                    MMA_F16(acc[mt][nt * 2 + 1], af[mt], bf[1], bf[3]);
                }
            }
        }
        __syncthreads();
    }

    // ---- epilogue 1: store Wh ----
#pragma unroll
    for (int mt = 0; mt < 2; mt++) {
        const int r0 = i0 + warp_m * 32 + mt * 16 + (lane >> 2);
#pragma unroll
        for (int nt = 0; nt < 8; nt++) {
            const int c = f0 + warp_n * 64 + nt * 8 + (lane & 3) * 2;
            *(float2*)(g_Wh + (size_t)r0 * HF_ + c) =
                make_float2(acc[mt][nt][0], acc[mt][nt][1]);
            *(float2*)(g_Wh + (size_t)(r0 + 8) * HF_ + c) =
                make_float2(acc[mt][nt][2], acc[mt][nt][3]);
        }
    }

    // ---- epilogue 2 (fused srcdst) ----
    const int h = blockIdx.y * 2 + warp_n;
    const int lq = lane & 3;
    float sp[4], dp[4];
#pragma unroll
    for (int mt = 0; mt < 2; mt++)
#pragma unroll
        for (int hf = 0; hf < 2; hf++) {
            float s = 0.f, d = 0.f;
#pragma unroll
            for (int nt = 0; nt < 8; nt++) {
                const int fi = nt * 8 + lq * 2;
                const float c0 = acc[mt][nt][hf * 2], c1 = acc[mt][nt][hf * 2 + 1];
                s += c0 * s_asrc[fi] + c1 * s_asrc[fi + 1];
                d += c0 * s_adst[fi] + c1 * s_adst[fi + 1];
            }
            sp[mt * 2 + hf] = s;
            dp[mt * 2 + hf] = d;
        }
#pragma unroll
    for (int q = 0; q < 4; q++) {
        sp[q] += __shfl_xor_sync(0xffffffffu, sp[q], 1);
        sp[q] += __shfl_xor_sync(0xffffffffu, sp[q], 2);
        dp[q] += __shfl_xor_sync(0xffffffffu, dp[q], 1);
        dp[q] += __shfl_xor_sync(0xffffffffu, dp[q], 2);
    }
    if (lq == 0) {
#pragma unroll
        for (int q = 0; q < 4; q++) {
            const int mt = q >> 1, hf = q & 1;
            const int row = i0 + warp_m * 32 + mt * 16 + hf * 8 + (lane >> 2);
            const int b = row >> 10, i = row & 1023;
            const int idx = (b * H_ + h) * S_ + i;
            const float s = sp[q], d = dp[q];
            g_ipack[idx] = make_float4(s, expf(s), expf(ALPHA_ * s), 0.f);
            const float m = mask[row] ? 1.f : 0.f;
            g_jpack[idx] = make_float4(d, m * expf(d), m * expf(ALPHA_ * d), 0.f);
        }
    }
}

// ---------------------------------------------------------------------------
// K2: per (b,h) hybrid bitonic sort -> sorted arrays in global.
// ---------------------------------------------------------------------------
__device__ __forceinline__ unsigned long long
bitonic_warp_tail(unsigned long long v, int t, int k, int jmax)
{
    const bool up = ((t & k) == 0);
#pragma unroll
    for (int j = 16; j > 0; j >>= 1) {
        if (j > jmax) continue;
        const unsigned long long p = __shfl_xor_sync(0xffffffffu, v, j);
        const bool lower = ((t & j) == 0);
        const bool keep_min = (lower == up);
        v = keep_min ? (v < p ? v : p) : (v > p ? v : p);
    }
    return v;
}

__global__ void __launch_bounds__(1024) sort_kernel()
{
    __shared__ unsigned long long sv[S_];
    const int bh = blockIdx.x;
    const int t  = threadIdx.x;

    unsigned long long v;
    {
        const uint32_t u = __float_as_uint(g_jpack[bh * S_ + t].x);
        const uint32_t s = (u & 0x80000000u) ? ~u : (u ^ 0x80000000u);
        v = ((unsigned long long)s << 32) | (unsigned)t;
    }
#pragma unroll
    for (int k = 2; k <= 32; k <<= 1)
        v = bitonic_warp_tail(v, t, k, k >> 1);
    sv[t] = v;
    __syncthreads();
    for (int k = 64; k <= S_; k <<= 1) {
        for (int j = k >> 1; j >= 32; j >>= 1) {
            const int ixj = t ^ j;
            if (ixj > t) {
                const bool up = ((t & k) == 0);
                const unsigned long long a = sv[t], b2 = sv[ixj];
                if (up ? (a > b2) : (a < b2)) { sv[t] = b2; sv[ixj] = a; }
            }
            __syncthreads();
        }
        v = sv[t];
        v = bitonic_warp_tail(v, t, k, 16);
        sv[t] = v;
        __syncthreads();
    }

    const int p = (int)(v & 0xFFFFFFFFu);
    const uint32_t s = (uint32_t)(v >> 32);
    const uint32_t u = (s & 0x80000000u) ? (s ^ 0x80000000u) : ~s;
    float4 jp = g_jpack[bh * S_ + p];
    g_dsorted[bh][t] = __uint_as_float(u);
    g_perm[bh][t]    = p;
    g_e1ds[bh][t]    = jp.y;
    g_eads[bh][t]    = jp.z;
}

// ---------------------------------------------------------------------------
// K3: scan. Block = (bh, col-half). 32 warps = 32 chunks; lane = column
// within the half. Chunk sums -> in-smem exclusive chunk scan -> Q arrays.
// half 1 additionally owns the Z (partition function) column (index 32).
// ---------------------------------------------------------------------------
__global__ void __launch_bounds__(1024) scan_kernel()
{
    __shared__ int   spm[S_];
    __shared__ float se0[S_], se1[S_];
    __shared__ float cs0[NCH_][34], cs1[NCH_][34];

    const int bh   = blockIdx.x;
    const int half = blockIdx.y;
    const int b = bh >> 3, h = bh & 7;
    const int t = threadIdx.x;

    for (int q = t; q < S_; q += 1024) {
        spm[q] = g_perm[bh][q] * HF_;
        se0[q] = g_eads[bh][q];
        se1[q] = g_e1ds[bh][q];
    }
    __syncthreads();

    const int w = t >> 5, lane = t & 31;
    const int col = half * 32 + lane;
    const float* __restrict__ whb = g_Wh + (size_t)b * S_ * HF_ + h * F_ + col;

    // ---- A: chunk partial sums ----
    {
        float s0 = 0.f, s1 = 0.f, z0 = 0.f, z1 = 0.f;
#pragma unroll 4
        for (int k = 0; k < CH_; k++) {
            const int kk = w * CH_ + k;
            const float w0 = se0[kk], w1 = se1[kk];
            const float v = __ldg(whb + spm[kk]);
            s0 += w0 * v; s1 += w1 * v;
            z0 += w0; z1 += w1;
        }
        cs0[w][lane] = s0; cs1[w][lane] = s1;
        if (half && lane == 0) { cs0[w][32] = z0; cs1[w][32] = z1; }
    }
    __syncthreads();

    // ---- B: exclusive scan of the 32 chunk sums per column ----
    const int ncol = half ? 33 : 32;
    if (t < ncol) {
        float a = 0.f;
#pragma unroll
        for (int ch = 0; ch < NCH_; ch++) {
            const float x = cs0[ch][t];
            cs0[ch][t] = a;
            a += x;
        }
    } else if (t >= 64 && t < 64 + ncol) {
        const int c = t - 64;
        float a = 0.f;
#pragma unroll
        for (int ch = 0; ch < NCH_; ch++) {
            const float x = cs1[ch][c];
            cs1[ch][c] = a;
            a += x;
        }
    }
    __syncthreads();

    // ---- C: materialize Q0/Q1 ----
    {
        float o0 = cs0[w][lane], o1 = cs1[w][lane];
        float oz0 = cs0[w][32],  oz1 = cs1[w][32];
#pragma unroll 4
        for (int k = 0; k < CH_; k++) {
            const int kk = w * CH_ + k;
            float* q0 = &g_Q0[bh][kk][0];
            float* q1 = &g_Q1[bh][kk][0];
            q0[col] = o0; q1[col] = o1;
            if (half && lane == 0) { q0[64] = oz0; q1[64] = oz1; }
            const float w0 = se0[kk], w1 = se1[kk];
            const float v = __ldg(whb + spm[kk]);
            o0 += w0 * v; o1 += w1 * v;
            oz0 += w0; oz1 += w1;
        }
        if (w == NCH_ - 1) {
            float* q0 = &g_Q0[bh][S_][0];
            float* q1 = &g_Q1[bh][S_][0];
            q0[col] = o0; q1[col] = o1;
            if (half && lane == 0) { q0[64] = oz0; q1[64] = oz1; }
        }
    }
}

// ---------------------------------------------------------------------------
// K4: output epilogue. Block = 32 i-rows x 16 f-quads (512 thr).
// ---------------------------------------------------------------------------
__global__ void __launch_bounds__(512) out_kernel(float* __restrict__ out)
{
    __shared__ float ds[S_];
    const int b = blockIdx.z, h = blockIdx.y;
    const int bh = b * H_ + h;
    const int t = threadIdx.x;

    for (int q = t; q < S_; q += 512) ds[q] = g_dsorted[bh][q];
    __syncthreads();

    const int c4 = t & 15;
    const int il = t >> 4;
    const int i  = blockIdx.x * 32 + il;

    float4 ip = g_ipack[bh * S_ + i];
    const float e1s = ip.y, eas = ip.z;
    const float thr = -ip.x;

    int lo = 0, hi = S_;
    while (lo < hi) {
        const int mid = (lo + hi) >> 1;
        if (ds[mid] < thr) lo = mid + 1; else hi = mid;
    }

    const float* q0 = &g_Q0[bh][lo][0];
    const float* q1 = &g_Q1[bh][lo][0];
    const float* t1 = &g_Q1[bh][S_][0];

    float4 n4 = *(const float4*)(q0 + c4 * 4);
    float4 q4 = *(const float4*)(q1 + c4 * 4);
    float4 t4 = *(const float4*)(t1 + c4 * 4);
    const float zpos = t1[64] - q1[64];
    const float inv = 1.f / (eas * q0[64] + e1s * zpos);

    float4 o;
    o.x = (eas * n4.x + e1s * (t4.x - q4.x)) * inv;
    o.y = (eas * n4.y + e1s * (t4.y - q4.y)) * inv;
    o.z = (eas * n4.z + e1s * (t4.z - q4.z)) * inv;
    o.w = (eas * n4.w + e1s * (t4.w - q4.w)) * inv;
    *(float4*)(out + (size_t)(b * S_ + i) * HF_ + h * F_ + c4 * 4) = o;
}

// ---------------------------------------------------------------------------
extern "C" void kernel_launch(void* const* d_in, const int* in_sizes, int n_in,
                              void* d_out, int out_size)
{
    const float* X    = (const float*)d_in[0];
    const int*   mask = (const int*)  d_in[1];
    const float* W    = (const float*)d_in[2];
    const float* a    = (const float*)d_in[3];
    float*       out  = (float*)d_out;

    static bool attr_set = false;
    if (!attr_set) {
        cudaFuncSetAttribute(mma_gemm_kernel,
                             cudaFuncAttributeMaxDynamicSharedMemorySize, 3 * STG_);
        attr_set = true;
    }

    conv_kernel<<<NXBLK_ + NWBLK_, 256>>>(X, W);
    mma_gemm_kernel<<<dim3((B_ * S_) / 128, HF_ / 128), 256, 3 * STG_>>>(mask, a);
    sort_kernel<<<BH_, 1024>>>();
    scan_kernel<<<dim3(BH_, 2), 1024>>>();
    out_kernel<<<dim3(S_ / 32, H_, B_), 512>>>(out);
}